// round 9
// baseline (speedup 1.0000x reference)
#include <cuda_runtime.h>
#include <cstdint>

// ---------------------------------------------------------------------------
// SpectraLoRA fused, mma.sync tf32, round 9:
//  - prologue rounds x, W, A to tf32 once (device buffers) -> no cvt in loop
//  - cp.async (16B, .cg) double-buffered smem, 1 syncthreads per K-tile
//  - 128-thread CTAs, warp tile 64x64 (2x2 warps) -> 1.0 LDS per MMA
//  - frozen K=768 GEMM + LoRA K=128 GEMM share one accumulator tile
// ---------------------------------------------------------------------------

#define IN_F   768
#define OUT_F  2304
#define NBATCH 8
#define M_TOT  16384
#define NE     8
#define NR     16
#define ERDIM  128
#define GD     64
#define SCALING 2.0f

#define BM 128
#define BN 128
#define BK 32
#define SPAD 36                   // words per smem row (32 data + 4 pad)
#define TILE_WORDS (BM * SPAD)    // 4608 words = 18432 B per tile buffer
#define SMEM_BYTES (4 * TILE_WORDS * 4)   // A0,A1,B0,B1 = 73728 B

__device__ float g_gate[NBATCH * NE];
__device__ float g_BmT[OUT_F * ERDIM];            // tf32-rounded
__device__ float g_h[(size_t)M_TOT * ERDIM];      // tf32-rounded
__device__ float g_xt[(size_t)M_TOT * IN_F];      // tf32-rounded x
__device__ float g_Wt[(size_t)OUT_F * IN_F];      // tf32-rounded W
__device__ float g_At[ERDIM * IN_F];              // tf32-rounded A

// ---- helpers ---------------------------------------------------------------
static __device__ __forceinline__ uint32_t f2tf32(float f) {
    uint32_t u;
    asm("cvt.rna.tf32.f32 %0, %1;" : "=r"(u) : "f"(f));
    return u;
}
static __device__ __forceinline__ void mma_tf32(float d[4], const uint32_t a[4],
                                                const uint32_t b[2]) {
    asm volatile(
        "mma.sync.aligned.m16n8k8.row.col.f32.tf32.tf32.f32 "
        "{%0,%1,%2,%3}, {%4,%5,%6,%7}, {%8,%9}, {%0,%1,%2,%3};"
        : "+f"(d[0]), "+f"(d[1]), "+f"(d[2]), "+f"(d[3])
        : "r"(a[0]), "r"(a[1]), "r"(a[2]), "r"(a[3]), "r"(b[0]), "r"(b[1]));
}
static __device__ __forceinline__ uint32_t smem_u32(const void* p) {
    uint32_t a;
    asm("{ .reg .u64 t; cvta.to.shared.u64 t, %1; cvt.u32.u64 %0, t; }"
        : "=r"(a) : "l"(p));
    return a;
}
static __device__ __forceinline__ void cpasync16(uint32_t dst, const void* src) {
    asm volatile("cp.async.cg.shared.global [%0], [%1], 16;"
                 :: "r"(dst), "l"(src) : "memory");
}
#define CP_COMMIT() asm volatile("cp.async.commit_group;" ::: "memory")
#define CP_WAIT0()  asm volatile("cp.async.wait_group 0;" ::: "memory")

// 128 threads: thread tid owns smem row tid, 8 x 16B cp.async per tile.
static __device__ __forceinline__ void load_tile(uint32_t sdst,
                                                 const float* __restrict__ src,
                                                 int ld, int row0, int k0,
                                                 int tid) {
    const float* gp = src + (size_t)(row0 + tid) * ld + k0;
    const uint32_t d = sdst + (uint32_t)tid * (SPAD * 4);
#pragma unroll
    for (int kq = 0; kq < 8; kq++)
        cpasync16(d + kq * 16, gp + kq * 4);
}

// warp tile 64x64 over one BK=32 slab; acc[4][8][4]
static __device__ __forceinline__ void compute_tile(const uint32_t (*As)[SPAD],
                                                    const uint32_t (*Bs)[SPAD],
                                                    int wm, int wn, int g, int t,
                                                    float acc[4][8][4]) {
#pragma unroll
    for (int kk = 0; kk < 4; kk++) {
        const int k8 = kk * 8;
        uint32_t af[4][4], bf[8][2];
#pragma unroll
        for (int mi = 0; mi < 4; mi++) {
            const int m = wm * 64 + mi * 16 + g;
            af[mi][0] = As[m][k8 + t];
            af[mi][1] = As[m + 8][k8 + t];
            af[mi][2] = As[m][k8 + t + 4];
            af[mi][3] = As[m + 8][k8 + t + 4];
        }
#pragma unroll
        for (int ni = 0; ni < 8; ni++) {
            const int n = wn * 64 + ni * 8 + g;
            bf[ni][0] = Bs[n][k8 + t];
            bf[ni][1] = Bs[n][k8 + t + 4];
        }
#pragma unroll
        for (int mi = 0; mi < 4; mi++)
#pragma unroll
            for (int ni = 0; ni < 8; ni++)
                mma_tf32(acc[mi][ni], af[mi], bf[ni]);
    }
}

// ---- prologue kernels ------------------------------------------------------
__global__ void cvt_kernel(const float4* __restrict__ s, float4* __restrict__ d,
                           int n4) {
    int i = blockIdx.x * blockDim.x + threadIdx.x;
    if (i < n4) {
        float4 v = s[i];
        v.x = __uint_as_float(f2tf32(v.x));
        v.y = __uint_as_float(f2tf32(v.y));
        v.z = __uint_as_float(f2tf32(v.z));
        v.w = __uint_as_float(f2tf32(v.w));
        d[i] = v;
    }
}

__global__ void gate_kernel(const float* __restrict__ z,
                            const float* __restrict__ Wg,
                            const float* __restrict__ bg) {
    __shared__ float sl[NBATCH][NE];
    int tid = threadIdx.x;
    int b = tid >> 3, e = tid & 7;
    float s = bg[e];
#pragma unroll
    for (int g = 0; g < GD; g++) s += z[b * GD + g] * Wg[e * GD + g];
    sl[b][e] = s;
    __syncthreads();
    if (tid < NBATCH) {
        int bb = tid;
        float mx = -1e30f;
        for (int k = 0; k < NE; k++) mx = fmaxf(mx, sl[bb][k]);
        float ex[NE]; float den = 0.f;
        for (int k = 0; k < NE; k++) { ex[k] = expf(sl[bb][k] - mx); den += ex[k]; }
        float inv = 1.f / den;
        for (int k = 0; k < NE; k++) g_gate[bb * NE + k] = ex[k] * inv;
    }
}

__global__ void bmt_kernel(const float* __restrict__ Bm) {
    int idx = blockIdx.x * blockDim.x + threadIdx.x;   // < OUT_F*ERDIM
    int o = idx >> 7, j = idx & 127;
    int e = j >> 4, r = j & 15;
    g_BmT[idx] = __uint_as_float(f2tf32(Bm[((size_t)e * OUT_F + o) * NR + r]));
}

// ---- kernel: g_h = round_tf32(SCALING * gate ⊙ (xt @ At^T)) ---------------
__global__ __launch_bounds__(128)
void h_mma_kernel() {
    extern __shared__ uint32_t smem[];
    const uint32_t sb = smem_u32(smem);
    const int tid = threadIdx.x, warp = tid >> 5, lane = tid & 31;
    const int wm = warp >> 1, wn = warp & 1;
    const int g = lane >> 2, t = lane & 3;
    const int m0 = blockIdx.x * BM;

    float acc[4][8][4];
#pragma unroll
    for (int i = 0; i < 4; i++)
#pragma unroll
        for (int j = 0; j < 8; j++)
#pragma unroll
            for (int r = 0; r < 4; r++) acc[i][j][r] = 0.f;

    load_tile(sb, g_xt, IN_F, m0, 0, tid);
    load_tile(sb + 2 * TILE_WORDS * 4, g_At, IN_F, 0, 0, tid);
    CP_COMMIT();

    const int T = IN_F / BK;   // 24
    for (int tt = 0; tt < T; tt++) {
        CP_WAIT0();
        __syncthreads();
        if (tt + 1 < T) {
            const uint32_t b = (uint32_t)((tt + 1) & 1) * (TILE_WORDS * 4);
            load_tile(sb + b, g_xt, IN_F, m0, (tt + 1) * BK, tid);
            load_tile(sb + 2 * TILE_WORDS * 4 + b, g_At, IN_F, 0, (tt + 1) * BK, tid);
            CP_COMMIT();
        }
        const uint32_t off = (uint32_t)(tt & 1) * TILE_WORDS;
        compute_tile((const uint32_t (*)[SPAD])(smem + off),
                     (const uint32_t (*)[SPAD])(smem + 2 * TILE_WORDS + off),
                     wm, wn, g, t, acc);
    }

    const int bt = m0 >> 11;            // 128-row tile lies in one batch
#pragma unroll
    for (int mi = 0; mi < 4; mi++) {
        const int row = m0 + wm * 64 + mi * 16 + g;
#pragma unroll
        for (int ni = 0; ni < 8; ni++) {
            const int col = wn * 64 + ni * 8 + 2 * t;   // even; pair same expert
            const float s = SCALING * g_gate[bt * NE + (col >> 4)];
            float2 v0, v1;
            v0.x = __uint_as_float(f2tf32(acc[mi][ni][0] * s));
            v0.y = __uint_as_float(f2tf32(acc[mi][ni][1] * s));
            v1.x = __uint_as_float(f2tf32(acc[mi][ni][2] * s));
            v1.y = __uint_as_float(f2tf32(acc[mi][ni][3] * s));
            *(float2*)(g_h + (size_t)row * ERDIM + col) = v0;
            *(float2*)(g_h + (size_t)(row + 8) * ERDIM + col) = v1;
        }
    }
}

// ---- kernel: out = xt@Wt^T + bias + g_h@BmT^T ------------------------------
__global__ __launch_bounds__(128)
void main_mma_kernel(const float* __restrict__ bias, float* __restrict__ out) {
    extern __shared__ uint32_t smem[];
    const uint32_t sb = smem_u32(smem);
    const int tid = threadIdx.x, warp = tid >> 5, lane = tid & 31;
    const int wm = warp >> 1, wn = warp & 1;
    const int g = lane >> 2, t = lane & 3;
    const int m0 = blockIdx.y * BM, n0 = blockIdx.x * BN;

    float acc[4][8][4];
#pragma unroll
    for (int i = 0; i < 4; i++)
#pragma unroll
        for (int j = 0; j < 8; j++)
#pragma unroll
            for (int r = 0; r < 4; r++) acc[i][j][r] = 0.f;

    load_tile(sb, g_xt, IN_F, m0, 0, tid);
    load_tile(sb + 2 * TILE_WORDS * 4, g_Wt, IN_F, n0, 0, tid);
    CP_COMMIT();

    const int T1 = IN_F / BK;           // 24 frozen tiles
    const int T = T1 + ERDIM / BK;      // + 4 LoRA tiles = 28
    for (int tt = 0; tt < T; tt++) {
        CP_WAIT0();
        __syncthreads();
        if (tt + 1 < T) {
            const uint32_t b = (uint32_t)((tt + 1) & 1) * (TILE_WORDS * 4);
            if (tt + 1 < T1) {
                load_tile(sb + b, g_xt, IN_F, m0, (tt + 1) * BK, tid);
                load_tile(sb + 2 * TILE_WORDS * 4 + b, g_Wt, IN_F, n0,
                          (tt + 1) * BK, tid);
            } else {
                load_tile(sb + b, g_h, ERDIM, m0, (tt + 1 - T1) * BK, tid);
                load_tile(sb + 2 * TILE_WORDS * 4 + b, g_BmT, ERDIM, n0,
                          (tt + 1 - T1) * BK, tid);
            }
            CP_COMMIT();
        }
        const uint32_t off = (uint32_t)(tt & 1) * TILE_WORDS;
        compute_tile((const uint32_t (*)[SPAD])(smem + off),
                     (const uint32_t (*)[SPAD])(smem + 2 * TILE_WORDS + off),
                     wm, wn, g, t, acc);
    }

#pragma unroll
    for (int mi = 0; mi < 4; mi++) {
        const int row = m0 + wm * 64 + mi * 16 + g;
#pragma unroll
        for (int ni = 0; ni < 8; ni++) {
            const int col = n0 + wn * 64 + ni * 8 + 2 * t;
            const float2 bb = *(const float2*)(bias + col);
            float2 v0 = make_float2(acc[mi][ni][0] + bb.x, acc[mi][ni][1] + bb.y);
            float2 v1 = make_float2(acc[mi][ni][2] + bb.x, acc[mi][ni][3] + bb.y);
            *(float2*)(out + (size_t)row * OUT_F + col) = v0;
            *(float2*)(out + (size_t)(row + 8) * OUT_F + col) = v1;
        }
    }
}

// ---------------------------------------------------------------------------
extern "C" void kernel_launch(void* const* d_in, const int* in_sizes, int n_in,
                              void* d_out, int out_size) {
    const float* x  = (const float*)d_in[0];   // [8,2048,768]
    const float* z  = (const float*)d_in[1];   // [8,64]
    const float* W  = (const float*)d_in[2];   // [2304,768]
    const float* b  = (const float*)d_in[3];   // [2304]
    const float* A  = (const float*)d_in[4];   // [8,16,768]
    const float* Bm = (const float*)d_in[5];   // [8,2304,16]
    const float* Wg = (const float*)d_in[6];   // [8,64]
    const float* bg = (const float*)d_in[7];   // [8]
    float* out = (float*)d_out;                // [8,2048,2304]

    static int attr_done = 0;
    if (!attr_done) {
        cudaFuncSetAttribute(h_mma_kernel,
                             cudaFuncAttributeMaxDynamicSharedMemorySize, SMEM_BYTES);
        cudaFuncSetAttribute(main_mma_kernel,
                             cudaFuncAttributeMaxDynamicSharedMemorySize, SMEM_BYTES);
        attr_done = 1;
    }

    float* xt = nullptr; float* Wt = nullptr; float* At = nullptr;
    cudaGetSymbolAddress((void**)&xt, g_xt);
    cudaGetSymbolAddress((void**)&Wt, g_Wt);
    cudaGetSymbolAddress((void**)&At, g_At);

    // prologue: tf32 pre-rounding + gate + BmT repack
    cvt_kernel<<<(M_TOT * IN_F / 4 + 1023) / 1024, 1024>>>(
        (const float4*)x, (float4*)xt, M_TOT * IN_F / 4);
    cvt_kernel<<<(OUT_F * IN_F / 4 + 1023) / 1024, 1024>>>(
        (const float4*)W, (float4*)Wt, OUT_F * IN_F / 4);
    cvt_kernel<<<(ERDIM * IN_F / 4 + 1023) / 1024, 1024>>>(
        (const float4*)A, (float4*)At, ERDIM * IN_F / 4);
    gate_kernel<<<1, 64>>>(z, Wg, bg);
    bmt_kernel<<<(OUT_F * ERDIM) / 1024, 1024>>>(Bm);

    // LoRA down-projection (gated, scaled, tf32-rounded)
    h_mma_kernel<<<M_TOT / BM, 128, SMEM_BYTES>>>();

    // fused frozen + LoRA up-projection
    main_mma_kernel<<<dim3(OUT_F / BN, M_TOT / BM), 128, SMEM_BYTES>>>(b, out);
}

// round 10
// speedup vs baseline: 1.6712x; 1.6712x over previous
#include <cuda_runtime.h>
#include <cstdint>

// ---------------------------------------------------------------------------
// SpectraLoRA fused, mma.sync tf32, round 10:
//   R8 shape (256-thread CTAs, warp tile 64x32, 16 warps/SM)
// + R9's pipeline ideas: tf32 pre-rounding prologue (no cvt in hot loop),
//   cp.async.cg double-buffered smem (no STS, one sync per K-tile).
//   frozen K=768 GEMM + LoRA K=128 GEMM share one accumulator tile.
// ---------------------------------------------------------------------------

#define IN_F   768
#define OUT_F  2304
#define NBATCH 8
#define M_TOT  16384
#define NE     8
#define NR     16
#define ERDIM  128
#define GD     64
#define SCALING 2.0f

#define BM 128
#define BN 128
#define BK 32
#define SPAD 36                   // words per smem row (32 data + 4 pad)
#define TILE_WORDS (BM * SPAD)    // 4608 words = 18432 B per tile buffer
#define SMEM_BYTES (4 * TILE_WORDS * 4)   // A0,A1,B0,B1 = 73728 B

__device__ float g_gate[NBATCH * NE];
__device__ float g_BmT[OUT_F * ERDIM];            // tf32-rounded
__device__ float g_h[(size_t)M_TOT * ERDIM];      // tf32-rounded
__device__ float g_xt[(size_t)M_TOT * IN_F];      // tf32-rounded x
__device__ float g_Wt[(size_t)OUT_F * IN_F];      // tf32-rounded W
__device__ float g_At[ERDIM * IN_F];              // tf32-rounded A

// ---- helpers ---------------------------------------------------------------
static __device__ __forceinline__ uint32_t f2tf32(float f) {
    uint32_t u;
    asm("cvt.rna.tf32.f32 %0, %1;" : "=r"(u) : "f"(f));
    return u;
}
static __device__ __forceinline__ void mma_tf32(float d[4], const uint32_t a[4],
                                                const uint32_t b[2]) {
    asm volatile(
        "mma.sync.aligned.m16n8k8.row.col.f32.tf32.tf32.f32 "
        "{%0,%1,%2,%3}, {%4,%5,%6,%7}, {%8,%9}, {%0,%1,%2,%3};"
        : "+f"(d[0]), "+f"(d[1]), "+f"(d[2]), "+f"(d[3])
        : "r"(a[0]), "r"(a[1]), "r"(a[2]), "r"(a[3]), "r"(b[0]), "r"(b[1]));
}
static __device__ __forceinline__ uint32_t smem_u32(const void* p) {
    uint32_t a;
    asm("{ .reg .u64 t; cvta.to.shared.u64 t, %1; cvt.u32.u64 %0, t; }"
        : "=r"(a) : "l"(p));
    return a;
}
static __device__ __forceinline__ void cpasync16(uint32_t dst, const void* src) {
    asm volatile("cp.async.cg.shared.global [%0], [%1], 16;"
                 :: "r"(dst), "l"(src) : "memory");
}
#define CP_COMMIT() asm volatile("cp.async.commit_group;" ::: "memory")
#define CP_WAIT0()  asm volatile("cp.async.wait_group 0;" ::: "memory")

// 256 threads: kq = tid&7 (16B column), r0 = tid>>3 (0..31); rows r0+32*i.
// Full 128x32 tile = 4 cp.async per thread, smem row-major stride SPAD.
static __device__ __forceinline__ void load_tile(uint32_t sdst,
                                                 const float* __restrict__ src,
                                                 int ld, int row0, int k0,
                                                 int tid) {
    const int kq = tid & 7, r0 = tid >> 3;
    const float* gp = src + (size_t)(row0 + r0) * ld + k0 + kq * 4;
    uint32_t d = sdst + ((uint32_t)r0 * SPAD + (uint32_t)kq * 4) * 4;
#pragma unroll
    for (int i = 0; i < 4; i++)
        cpasync16(d + i * (32 * SPAD * 4), gp + (size_t)(32 * i) * ld);
}

// warp tile 64x32 over one BK=32 slab; acc[4][4][4]
static __device__ __forceinline__ void compute_tile(const uint32_t (*As)[SPAD],
                                                    const uint32_t (*Bs)[SPAD],
                                                    int wm, int wn, int g, int t,
                                                    float acc[4][4][4]) {
#pragma unroll
    for (int kk = 0; kk < 4; kk++) {
        const int k8 = kk * 8;
        uint32_t af[4][4], bf[4][2];
#pragma unroll
        for (int mi = 0; mi < 4; mi++) {
            const int m = wm * 64 + mi * 16 + g;
            af[mi][0] = As[m][k8 + t];
            af[mi][1] = As[m + 8][k8 + t];
            af[mi][2] = As[m][k8 + t + 4];
            af[mi][3] = As[m + 8][k8 + t + 4];
        }
#pragma unroll
        for (int ni = 0; ni < 4; ni++) {
            const int n = wn * 32 + ni * 8 + g;
            bf[ni][0] = Bs[n][k8 + t];
            bf[ni][1] = Bs[n][k8 + t + 4];
        }
#pragma unroll
        for (int mi = 0; mi < 4; mi++)
#pragma unroll
            for (int ni = 0; ni < 4; ni++)
                mma_tf32(acc[mi][ni], af[mi], bf[ni]);
    }
}

// ---- prologue kernels ------------------------------------------------------
__global__ void cvt_kernel(const float4* __restrict__ s, float4* __restrict__ d,
                           int n4) {
    int i = blockIdx.x * blockDim.x + threadIdx.x;
    if (i < n4) {
        float4 v = s[i];
        v.x = __uint_as_float(f2tf32(v.x));
        v.y = __uint_as_float(f2tf32(v.y));
        v.z = __uint_as_float(f2tf32(v.z));
        v.w = __uint_as_float(f2tf32(v.w));
        d[i] = v;
    }
}

__global__ void gate_kernel(const float* __restrict__ z,
                            const float* __restrict__ Wg,
                            const float* __restrict__ bg) {
    __shared__ float sl[NBATCH][NE];
    int tid = threadIdx.x;
    int b = tid >> 3, e = tid & 7;
    float s = bg[e];
#pragma unroll
    for (int g = 0; g < GD; g++) s += z[b * GD + g] * Wg[e * GD + g];
    sl[b][e] = s;
    __syncthreads();
    if (tid < NBATCH) {
        int bb = tid;
        float mx = -1e30f;
        for (int k = 0; k < NE; k++) mx = fmaxf(mx, sl[bb][k]);
        float ex[NE]; float den = 0.f;
        for (int k = 0; k < NE; k++) { ex[k] = expf(sl[bb][k] - mx); den += ex[k]; }
        float inv = 1.f / den;
        for (int k = 0; k < NE; k++) g_gate[bb * NE + k] = ex[k] * inv;
    }
}

__global__ void bmt_kernel(const float* __restrict__ Bm) {
    int idx = blockIdx.x * blockDim.x + threadIdx.x;   // < OUT_F*ERDIM
    int o = idx >> 7, j = idx & 127;
    int e = j >> 4, r = j & 15;
    g_BmT[idx] = __uint_as_float(f2tf32(Bm[((size_t)e * OUT_F + o) * NR + r]));
}

// ---- kernel: g_h = round_tf32(SCALING * gate ⊙ (xt @ At^T)) ---------------
__global__ __launch_bounds__(256)
void h_mma_kernel() {
    extern __shared__ uint32_t smem[];
    const uint32_t sb = smem_u32(smem);
    const int tid = threadIdx.x, warp = tid >> 5, lane = tid & 31;
    const int wm = warp >> 2, wn = warp & 3;
    const int g = lane >> 2, t = lane & 3;
    const int m0 = blockIdx.x * BM;

    float acc[4][4][4];
#pragma unroll
    for (int i = 0; i < 4; i++)
#pragma unroll
        for (int j = 0; j < 4; j++)
#pragma unroll
            for (int r = 0; r < 4; r++) acc[i][j][r] = 0.f;

    load_tile(sb, g_xt, IN_F, m0, 0, tid);
    load_tile(sb + 2 * TILE_WORDS * 4, g_At, IN_F, 0, 0, tid);
    CP_COMMIT();

    const int T = IN_F / BK;   // 24
    for (int tt = 0; tt < T; tt++) {
        CP_WAIT0();
        __syncthreads();
        if (tt + 1 < T) {
            const uint32_t b = (uint32_t)((tt + 1) & 1) * (TILE_WORDS * 4);
            load_tile(sb + b, g_xt, IN_F, m0, (tt + 1) * BK, tid);
            load_tile(sb + 2 * TILE_WORDS * 4 + b, g_At, IN_F, 0, (tt + 1) * BK, tid);
            CP_COMMIT();
        }
        const uint32_t off = (uint32_t)(tt & 1) * TILE_WORDS;
        compute_tile((const uint32_t (*)[SPAD])(smem + off),
                     (const uint32_t (*)[SPAD])(smem + 2 * TILE_WORDS + off),
                     wm, wn, g, t, acc);
        __syncthreads();
    }

    const int bt = m0 >> 11;            // 128-row tile lies in one batch
#pragma unroll
    for (int mi = 0; mi < 4; mi++) {
        const int row = m0 + wm * 64 + mi * 16 + g;
#pragma unroll
        for (int ni = 0; ni < 4; ni++) {
            const int col = wn * 32 + ni * 8 + 2 * t;   // even; pair same expert
            const float s = SCALING * g_gate[bt * NE + (col >> 4)];
            float2 v0, v1;
            v0.x = __uint_as_float(f2tf32(acc[mi][ni][0] * s));
            v0.y = __uint_as_float(f2tf32(acc[mi][ni][1] * s));
            v1.x = __uint_as_float(f2tf32(acc[mi][ni][2] * s));
            v1.y = __uint_as_float(f2tf32(acc[mi][ni][3] * s));
            *(float2*)(g_h + (size_t)row * ERDIM + col) = v0;
            *(float2*)(g_h + (size_t)(row + 8) * ERDIM + col) = v1;
        }
    }
}

// ---- kernel: out = xt@Wt^T + bias + g_h@BmT^T ------------------------------
__global__ __launch_bounds__(256)
void main_mma_kernel(const float* __restrict__ bias, float* __restrict__ out) {
    extern __shared__ uint32_t smem[];
    const uint32_t sb = smem_u32(smem);
    const int tid = threadIdx.x, warp = tid >> 5, lane = tid & 31;
    const int wm = warp >> 2, wn = warp & 3;
    const int g = lane >> 2, t = lane & 3;
    const int m0 = blockIdx.y * BM, n0 = blockIdx.x * BN;

    float acc[4][4][4];
#pragma unroll
    for (int i = 0; i < 4; i++)
#pragma unroll
        for (int j = 0; j < 4; j++)
#pragma unroll
            for (int r = 0; r < 4; r++) acc[i][j][r] = 0.f;

    load_tile(sb, g_xt, IN_F, m0, 0, tid);
    load_tile(sb + 2 * TILE_WORDS * 4, g_Wt, IN_F, n0, 0, tid);
    CP_COMMIT();

    const int T1 = IN_F / BK;           // 24 frozen tiles
    const int T = T1 + ERDIM / BK;      // + 4 LoRA tiles = 28
    for (int tt = 0; tt < T; tt++) {
        CP_WAIT0();
        __syncthreads();
        if (tt + 1 < T) {
            const uint32_t b = (uint32_t)((tt + 1) & 1) * (TILE_WORDS * 4);
            if (tt + 1 < T1) {
                load_tile(sb + b, g_xt, IN_F, m0, (tt + 1) * BK, tid);
                load_tile(sb + 2 * TILE_WORDS * 4 + b, g_Wt, IN_F, n0,
                          (tt + 1) * BK, tid);
            } else {
                load_tile(sb + b, g_h, ERDIM, m0, (tt + 1 - T1) * BK, tid);
                load_tile(sb + 2 * TILE_WORDS * 4 + b, g_BmT, ERDIM, n0,
                          (tt + 1 - T1) * BK, tid);
            }
            CP_COMMIT();
        }
        const uint32_t off = (uint32_t)(tt & 1) * TILE_WORDS;
        compute_tile((const uint32_t (*)[SPAD])(smem + off),
                     (const uint32_t (*)[SPAD])(smem + 2 * TILE_WORDS + off),
                     wm, wn, g, t, acc);
        __syncthreads();
    }

#pragma unroll
    for (int mi = 0; mi < 4; mi++) {
        const int row = m0 + wm * 64 + mi * 16 + g;
#pragma unroll
        for (int ni = 0; ni < 4; ni++) {
            const int col = n0 + wn * 32 + ni * 8 + 2 * t;
            const float2 bb = *(const float2*)(bias + col);
            float2 v0 = make_float2(acc[mi][ni][0] + bb.x, acc[mi][ni][1] + bb.y);
            float2 v1 = make_float2(acc[mi][ni][2] + bb.x, acc[mi][ni][3] + bb.y);
            *(float2*)(out + (size_t)row * OUT_F + col) = v0;
            *(float2*)(out + (size_t)(row + 8) * OUT_F + col) = v1;
        }
    }
}

// ---------------------------------------------------------------------------
extern "C" void kernel_launch(void* const* d_in, const int* in_sizes, int n_in,
                              void* d_out, int out_size) {
    const float* x  = (const float*)d_in[0];   // [8,2048,768]
    const float* z  = (const float*)d_in[1];   // [8,64]
    const float* W  = (const float*)d_in[2];   // [2304,768]
    const float* b  = (const float*)d_in[3];   // [2304]
    const float* A  = (const float*)d_in[4];   // [8,16,768]
    const float* Bm = (const float*)d_in[5];   // [8,2304,16]
    const float* Wg = (const float*)d_in[6];   // [8,64]
    const float* bg = (const float*)d_in[7];   // [8]
    float* out = (float*)d_out;                // [8,2048,2304]

    static int attr_done = 0;
    if (!attr_done) {
        cudaFuncSetAttribute(h_mma_kernel,
                             cudaFuncAttributeMaxDynamicSharedMemorySize, SMEM_BYTES);
        cudaFuncSetAttribute(main_mma_kernel,
                             cudaFuncAttributeMaxDynamicSharedMemorySize, SMEM_BYTES);
        attr_done = 1;
    }

    float* xt = nullptr; float* Wt = nullptr; float* At = nullptr;
    cudaGetSymbolAddress((void**)&xt, g_xt);
    cudaGetSymbolAddress((void**)&Wt, g_Wt);
    cudaGetSymbolAddress((void**)&At, g_At);

    // prologue: tf32 pre-rounding + gate + BmT repack
    cvt_kernel<<<(M_TOT * IN_F / 4 + 1023) / 1024, 1024>>>(
        (const float4*)x, (float4*)xt, M_TOT * IN_F / 4);
    cvt_kernel<<<(OUT_F * IN_F / 4 + 1023) / 1024, 1024>>>(
        (const float4*)W, (float4*)Wt, OUT_F * IN_F / 4);
    cvt_kernel<<<(ERDIM * IN_F / 4 + 1023) / 1024, 1024>>>(
        (const float4*)A, (float4*)At, ERDIM * IN_F / 4);
    gate_kernel<<<1, 64>>>(z, Wg, bg);
    bmt_kernel<<<(OUT_F * ERDIM) / 1024, 1024>>>(Bm);

    // LoRA down-projection (gated, scaled, tf32-rounded)
    h_mma_kernel<<<M_TOT / BM, 256, SMEM_BYTES>>>();

    // fused frozen + LoRA up-projection
    main_mma_kernel<<<dim3(OUT_F / BN, M_TOT / BM), 256, SMEM_BYTES>>>(b, out);
}

// round 11
// speedup vs baseline: 1.7083x; 1.0222x over previous
#include <cuda_runtime.h>
#include <cstdint>

// ---------------------------------------------------------------------------
// SpectraLoRA fused, mma.sync tf32, round 11:
//   R10 shape (256-thread CTAs, warp tile 64x32, 2 CTAs/SM, 16 warps/SM)
//   + 3-stage cp.async pipeline (wait_group 1), ONE __syncthreads per K-tile
//   + all prologue work fused into one prep_kernel (cvt x/W/A + BmT + gate)
//   frozen K=768 GEMM + LoRA K=128 GEMM share one accumulator tile.
// ---------------------------------------------------------------------------

#define IN_F   768
#define OUT_F  2304
#define NBATCH 8
#define M_TOT  16384
#define NE     8
#define NR     16
#define ERDIM  128
#define GD     64
#define SCALING 2.0f

#define BM 128
#define BN 128
#define BK 32
#define SPAD 36                   // words per smem row (32 data + 4 pad)
#define TILE_WORDS (BM * SPAD)    // 4608 words = 18432 B per tile buffer
#define NSTAGE 3
#define SMEM_BYTES (2 * NSTAGE * TILE_WORDS * 4)   // A0-2,B0-2 = 110592 B

__device__ float g_gate[NBATCH * NE];
__device__ float g_BmT[OUT_F * ERDIM];            // tf32-rounded
__device__ float g_h[(size_t)M_TOT * ERDIM];      // tf32-rounded
__device__ float g_xt[(size_t)M_TOT * IN_F];      // tf32-rounded x
__device__ float g_Wt[(size_t)OUT_F * IN_F];      // tf32-rounded W
__device__ float g_At[ERDIM * IN_F];              // tf32-rounded A

// ---- helpers ---------------------------------------------------------------
static __device__ __forceinline__ uint32_t f2tf32(float f) {
    uint32_t u;
    asm("cvt.rna.tf32.f32 %0, %1;" : "=r"(u) : "f"(f));
    return u;
}
static __device__ __forceinline__ void mma_tf32(float d[4], const uint32_t a[4],
                                                const uint32_t b[2]) {
    asm volatile(
        "mma.sync.aligned.m16n8k8.row.col.f32.tf32.tf32.f32 "
        "{%0,%1,%2,%3}, {%4,%5,%6,%7}, {%8,%9}, {%0,%1,%2,%3};"
        : "+f"(d[0]), "+f"(d[1]), "+f"(d[2]), "+f"(d[3])
        : "r"(a[0]), "r"(a[1]), "r"(a[2]), "r"(a[3]), "r"(b[0]), "r"(b[1]));
}
static __device__ __forceinline__ uint32_t smem_u32(const void* p) {
    uint32_t a;
    asm("{ .reg .u64 t; cvta.to.shared.u64 t, %1; cvt.u32.u64 %0, t; }"
        : "=r"(a) : "l"(p));
    return a;
}
static __device__ __forceinline__ void cpasync16(uint32_t dst, const void* src) {
    asm volatile("cp.async.cg.shared.global [%0], [%1], 16;"
                 :: "r"(dst), "l"(src) : "memory");
}
#define CP_COMMIT() asm volatile("cp.async.commit_group;" ::: "memory")
#define CP_WAIT1()  asm volatile("cp.async.wait_group 1;" ::: "memory")

// 256 threads: kq = tid&7 (16B column), r0 = tid>>3 (0..31); rows r0+32*i.
// Full 128x32 tile = 4 cp.async per thread, smem row-major stride SPAD.
static __device__ __forceinline__ void load_tile(uint32_t sdst,
                                                 const float* __restrict__ src,
                                                 int ld, int row0, int k0,
                                                 int tid) {
    const int kq = tid & 7, r0 = tid >> 3;
    const float* gp = src + (size_t)(row0 + r0) * ld + k0 + kq * 4;
    uint32_t d = sdst + ((uint32_t)r0 * SPAD + (uint32_t)kq * 4) * 4;
#pragma unroll
    for (int i = 0; i < 4; i++)
        cpasync16(d + i * (32 * SPAD * 4), gp + (size_t)(32 * i) * ld);
}

// warp tile 64x32 over one BK=32 slab; acc[4][4][4]
static __device__ __forceinline__ void compute_tile(const uint32_t (*As)[SPAD],
                                                    const uint32_t (*Bs)[SPAD],
                                                    int wm, int wn, int g, int t,
                                                    float acc[4][4][4]) {
#pragma unroll
    for (int kk = 0; kk < 4; kk++) {
        const int k8 = kk * 8;
        uint32_t af[4][4], bf[4][2];
#pragma unroll
        for (int mi = 0; mi < 4; mi++) {
            const int m = wm * 64 + mi * 16 + g;
            af[mi][0] = As[m][k8 + t];
            af[mi][1] = As[m + 8][k8 + t];
            af[mi][2] = As[m][k8 + t + 4];
            af[mi][3] = As[m + 8][k8 + t + 4];
        }
#pragma unroll
        for (int ni = 0; ni < 4; ni++) {
            const int n = wn * 32 + ni * 8 + g;
            bf[ni][0] = Bs[n][k8 + t];
            bf[ni][1] = Bs[n][k8 + t + 4];
        }
#pragma unroll
        for (int mi = 0; mi < 4; mi++)
#pragma unroll
            for (int ni = 0; ni < 4; ni++)
                mma_tf32(acc[mi][ni], af[mi], bf[ni]);
    }
}

// ---- fused prologue: cvt x/W/A to tf32, BmT repack, gate softmax -----------
#define N4X (M_TOT * IN_F / 4)
#define N4W (OUT_F * IN_F / 4)
#define N4A (ERDIM * IN_F / 4)
#define N4TOT (N4X + N4W + N4A)
#define NBMT (OUT_F * ERDIM)

__global__ void prep_kernel(const float* __restrict__ x,
                            const float* __restrict__ W,
                            const float* __restrict__ A,
                            const float* __restrict__ Bm,
                            const float* __restrict__ z,
                            const float* __restrict__ Wg,
                            const float* __restrict__ bg) {
    const int stride = gridDim.x * blockDim.x;
    // tf32-round x, W, A (vec4 grid-stride)
    for (int i = blockIdx.x * blockDim.x + threadIdx.x; i < N4TOT; i += stride) {
        const float4* s; float4* d; int j = i;
        if (j < N4X)            { s = (const float4*)x + j; d = (float4*)g_xt + j; }
        else if ((j -= N4X) < N4W) { s = (const float4*)W + j; d = (float4*)g_Wt + j; }
        else { j -= N4W;           s = (const float4*)A + j; d = (float4*)g_At + j; }
        float4 v = *s;
        v.x = __uint_as_float(f2tf32(v.x));
        v.y = __uint_as_float(f2tf32(v.y));
        v.z = __uint_as_float(f2tf32(v.z));
        v.w = __uint_as_float(f2tf32(v.w));
        *d = v;
    }
    // BmT[o][e*16+r] = round(Bm[e][o][r])
    for (int i = blockIdx.x * blockDim.x + threadIdx.x; i < NBMT; i += stride) {
        int o = i >> 7, j = i & 127;
        int e = j >> 4, r = j & 15;
        g_BmT[i] = __uint_as_float(f2tf32(Bm[((size_t)e * OUT_F + o) * NR + r]));
    }
    // gate softmax (block 0 only)
    if (blockIdx.x == 0) {
        __shared__ float sl[NBATCH][NE];
        int tid = threadIdx.x;
        if (tid < 64) {
            int b = tid >> 3, e = tid & 7;
            float s = bg[e];
#pragma unroll
            for (int g = 0; g < GD; g++) s += z[b * GD + g] * Wg[e * GD + g];
            sl[b][e] = s;
        }
        __syncthreads();
        if (tid < NBATCH) {
            float mx = -1e30f;
            for (int k = 0; k < NE; k++) mx = fmaxf(mx, sl[tid][k]);
            float ex[NE]; float den = 0.f;
            for (int k = 0; k < NE; k++) { ex[k] = expf(sl[tid][k] - mx); den += ex[k]; }
            float inv = 1.f / den;
            for (int k = 0; k < NE; k++) g_gate[tid * NE + k] = ex[k] * inv;
        }
    }
}

// ---- kernel: g_h = round_tf32(SCALING * gate ⊙ (xt @ At^T)) ---------------
__global__ __launch_bounds__(256, 2)
void h_mma_kernel() {
    extern __shared__ uint32_t smem[];
    const uint32_t sb = smem_u32(smem);
    const int tid = threadIdx.x, warp = tid >> 5, lane = tid & 31;
    const int wm = warp >> 2, wn = warp & 3;
    const int g = lane >> 2, t = lane & 3;
    const int m0 = blockIdx.x * BM;

    float acc[4][4][4];
#pragma unroll
    for (int i = 0; i < 4; i++)
#pragma unroll
        for (int j = 0; j < 4; j++)
#pragma unroll
            for (int r = 0; r < 4; r++) acc[i][j][r] = 0.f;

    const int T = IN_F / BK;   // 24
    // prologue: stages 0,1
#pragma unroll
    for (int s = 0; s < 2; s++) {
        load_tile(sb + s * (TILE_WORDS * 4), g_xt, IN_F, m0, s * BK, tid);
        load_tile(sb + (NSTAGE + s) * (TILE_WORDS * 4), g_At, IN_F, 0, s * BK, tid);
        CP_COMMIT();
    }
    for (int tt = 0; tt < T; tt++) {
        CP_WAIT1();
        __syncthreads();
        const int ts = tt + 2;
        if (ts < T) {
            const int s = ts % NSTAGE;
            load_tile(sb + s * (TILE_WORDS * 4), g_xt, IN_F, m0, ts * BK, tid);
            load_tile(sb + (NSTAGE + s) * (TILE_WORDS * 4), g_At, IN_F, 0, ts * BK, tid);
        }
        CP_COMMIT();
        const int c = tt % NSTAGE;
        compute_tile((const uint32_t (*)[SPAD])(smem + c * TILE_WORDS),
                     (const uint32_t (*)[SPAD])(smem + (NSTAGE + c) * TILE_WORDS),
                     wm, wn, g, t, acc);
    }

    const int bt = m0 >> 11;            // 128-row tile lies in one batch
#pragma unroll
    for (int mi = 0; mi < 4; mi++) {
        const int row = m0 + wm * 64 + mi * 16 + g;
#pragma unroll
        for (int ni = 0; ni < 4; ni++) {
            const int col = wn * 32 + ni * 8 + 2 * t;   // even; pair same expert
            const float s = SCALING * g_gate[bt * NE + (col >> 4)];
            float2 v0, v1;
            v0.x = __uint_as_float(f2tf32(acc[mi][ni][0] * s));
            v0.y = __uint_as_float(f2tf32(acc[mi][ni][1] * s));
            v1.x = __uint_as_float(f2tf32(acc[mi][ni][2] * s));
            v1.y = __uint_as_float(f2tf32(acc[mi][ni][3] * s));
            *(float2*)(g_h + (size_t)row * ERDIM + col) = v0;
            *(float2*)(g_h + (size_t)(row + 8) * ERDIM + col) = v1;
        }
    }
}

// ---- kernel: out = xt@Wt^T + bias + g_h@BmT^T ------------------------------
static __device__ __forceinline__ void main_load_stage(uint32_t sb, int ts,
                                                       int m0, int n0, int tid) {
    const int s = ts % NSTAGE;
    if (ts < IN_F / BK) {
        load_tile(sb + s * (TILE_WORDS * 4), g_xt, IN_F, m0, ts * BK, tid);
        load_tile(sb + (NSTAGE + s) * (TILE_WORDS * 4), g_Wt, IN_F, n0, ts * BK, tid);
    } else {
        const int k0 = (ts - IN_F / BK) * BK;
        load_tile(sb + s * (TILE_WORDS * 4), g_h, ERDIM, m0, k0, tid);
        load_tile(sb + (NSTAGE + s) * (TILE_WORDS * 4), g_BmT, ERDIM, n0, k0, tid);
    }
}

__global__ __launch_bounds__(256, 2)
void main_mma_kernel(const float* __restrict__ bias, float* __restrict__ out) {
    extern __shared__ uint32_t smem[];
    const uint32_t sb = smem_u32(smem);
    const int tid = threadIdx.x, warp = tid >> 5, lane = tid & 31;
    const int wm = warp >> 2, wn = warp & 3;
    const int g = lane >> 2, t = lane & 3;
    const int m0 = blockIdx.y * BM, n0 = blockIdx.x * BN;

    float acc[4][4][4];
#pragma unroll
    for (int i = 0; i < 4; i++)
#pragma unroll
        for (int j = 0; j < 4; j++)
#pragma unroll
            for (int r = 0; r < 4; r++) acc[i][j][r] = 0.f;

    const int T = IN_F / BK + ERDIM / BK;   // 24 + 4 = 28
    // prologue: stages 0,1
#pragma unroll
    for (int s = 0; s < 2; s++) {
        main_load_stage(sb, s, m0, n0, tid);
        CP_COMMIT();
    }
    for (int tt = 0; tt < T; tt++) {
        CP_WAIT1();
        __syncthreads();
        if (tt + 2 < T) main_load_stage(sb, tt + 2, m0, n0, tid);
        CP_COMMIT();
        const int c = tt % NSTAGE;
        compute_tile((const uint32_t (*)[SPAD])(smem + c * TILE_WORDS),
                     (const uint32_t (*)[SPAD])(smem + (NSTAGE + c) * TILE_WORDS),
                     wm, wn, g, t, acc);
    }

#pragma unroll
    for (int mi = 0; mi < 4; mi++) {
        const int row = m0 + wm * 64 + mi * 16 + g;
#pragma unroll
        for (int ni = 0; ni < 4; ni++) {
            const int col = n0 + wn * 32 + ni * 8 + 2 * t;
            const float2 bb = *(const float2*)(bias + col);
            float2 v0 = make_float2(acc[mi][ni][0] + bb.x, acc[mi][ni][1] + bb.y);
            float2 v1 = make_float2(acc[mi][ni][2] + bb.x, acc[mi][ni][3] + bb.y);
            *(float2*)(out + (size_t)row * OUT_F + col) = v0;
            *(float2*)(out + (size_t)(row + 8) * OUT_F + col) = v1;
        }
    }
}

// ---------------------------------------------------------------------------
extern "C" void kernel_launch(void* const* d_in, const int* in_sizes, int n_in,
                              void* d_out, int out_size) {
    const float* x  = (const float*)d_in[0];   // [8,2048,768]
    const float* z  = (const float*)d_in[1];   // [8,64]
    const float* W  = (const float*)d_in[2];   // [2304,768]
    const float* b  = (const float*)d_in[3];   // [2304]
    const float* A  = (const float*)d_in[4];   // [8,16,768]
    const float* Bm = (const float*)d_in[5];   // [8,2304,16]
    const float* Wg = (const float*)d_in[6];   // [8,64]
    const float* bg = (const float*)d_in[7];   // [8]
    float* out = (float*)d_out;                // [8,2048,2304]

    static int attr_done = 0;
    if (!attr_done) {
        cudaFuncSetAttribute(h_mma_kernel,
                             cudaFuncAttributeMaxDynamicSharedMemorySize, SMEM_BYTES);
        cudaFuncSetAttribute(main_mma_kernel,
                             cudaFuncAttributeMaxDynamicSharedMemorySize, SMEM_BYTES);
        attr_done = 1;
    }

    // fused prologue (tf32 rounding of x/W/A + BmT repack + gate softmax)
    prep_kernel<<<1184, 1024>>>(x, W, A, Bm, z, Wg, bg);

    // LoRA down-projection (gated, scaled, tf32-rounded)
    h_mma_kernel<<<M_TOT / BM, 256, SMEM_BYTES>>>();

    // fused frozen + LoRA up-projection
    main_mma_kernel<<<dim3(OUT_F / BN, M_TOT / BM), 256, SMEM_BYTES>>>(b, out);
}

// round 12
// speedup vs baseline: 1.7146x; 1.0037x over previous
#include <cuda_runtime.h>
#include <cstdint>

// ---------------------------------------------------------------------------
// SpectraLoRA fused, mma.sync tf32, round 12:
//   main GEMM: BM=128, BN=256, 256 threads, warp tile 64x64 (2x4 warps)
//   -> smem crossbar phases per MMA drop 1.5 -> 1.0 (the R11 binder)
//   3-stage cp.async pipeline (wait_group 1), one __syncthreads per K-tile.
//   frozen K=768 GEMM + LoRA K=128 GEMM share one accumulator tile.
// ---------------------------------------------------------------------------

#define IN_F   768
#define OUT_F  2304
#define NBATCH 8
#define M_TOT  16384
#define NE     8
#define NR     16
#define ERDIM  128
#define GD     64
#define SCALING 2.0f

#define BK 32
#define SPAD 36                         // words per smem row (32 data + 4 pad)
#define NSTAGE 3

// ---- h kernel tiles (128x128, warp 64x32, as R11) ----
#define H_BM 128
#define H_TILE_WORDS (H_BM * SPAD)      // 4608
#define H_SMEM_BYTES (2 * NSTAGE * H_TILE_WORDS * 4)   // 110592

// ---- main kernel tiles (128x256, warp 64x64) ----
#define M_BM 128
#define M_BN 256
#define TA_WORDS (M_BM * SPAD)          // 4608
#define TB_WORDS (M_BN * SPAD)          // 9216
#define STAGE_WORDS (TA_WORDS + TB_WORDS)
#define M_SMEM_BYTES (NSTAGE * STAGE_WORDS * 4)        // 165888

__device__ float g_gate[NBATCH * NE];
__device__ float g_BmT[OUT_F * ERDIM];            // tf32-rounded
__device__ float g_h[(size_t)M_TOT * ERDIM];      // tf32-rounded
__device__ float g_xt[(size_t)M_TOT * IN_F];      // tf32-rounded x
__device__ float g_Wt[(size_t)OUT_F * IN_F];      // tf32-rounded W
__device__ float g_At[ERDIM * IN_F];              // tf32-rounded A

// ---- helpers ---------------------------------------------------------------
static __device__ __forceinline__ uint32_t f2tf32(float f) {
    uint32_t u;
    asm("cvt.rna.tf32.f32 %0, %1;" : "=r"(u) : "f"(f));
    return u;
}
static __device__ __forceinline__ void mma_tf32(float d[4], const uint32_t a[4],
                                                const uint32_t b[2]) {
    asm volatile(
        "mma.sync.aligned.m16n8k8.row.col.f32.tf32.tf32.f32 "
        "{%0,%1,%2,%3}, {%4,%5,%6,%7}, {%8,%9}, {%0,%1,%2,%3};"
        : "+f"(d[0]), "+f"(d[1]), "+f"(d[2]), "+f"(d[3])
        : "r"(a[0]), "r"(a[1]), "r"(a[2]), "r"(a[3]), "r"(b[0]), "r"(b[1]));
}
static __device__ __forceinline__ uint32_t smem_u32(const void* p) {
    uint32_t a;
    asm("{ .reg .u64 t; cvta.to.shared.u64 t, %1; cvt.u32.u64 %0, t; }"
        : "=r"(a) : "l"(p));
    return a;
}
static __device__ __forceinline__ void cpasync16(uint32_t dst, const void* src) {
    asm volatile("cp.async.cg.shared.global [%0], [%1], 16;"
                 :: "r"(dst), "l"(src) : "memory");
}
#define CP_COMMIT() asm volatile("cp.async.commit_group;" ::: "memory")
#define CP_WAIT1()  asm volatile("cp.async.wait_group 1;" ::: "memory")

// 256 threads load a ROWSx32 fp32 tile: kq = tid&7 (16B col), r0 = tid>>3,
// rows r0 + 32*i. smem row-major stride SPAD.
template <int ROWS>
static __device__ __forceinline__ void load_tile(uint32_t sdst,
                                                 const float* __restrict__ src,
                                                 int ld, int row0, int k0,
                                                 int tid) {
    const int kq = tid & 7, r0 = tid >> 3;
    const float* gp = src + (size_t)(row0 + r0) * ld + k0 + kq * 4;
    uint32_t d = sdst + ((uint32_t)r0 * SPAD + (uint32_t)kq * 4) * 4;
#pragma unroll
    for (int i = 0; i < ROWS / 32; i++)
        cpasync16(d + i * (32 * SPAD * 4), gp + (size_t)(32 * i) * ld);
}

// ---- fused prologue: cvt x/W/A to tf32, BmT repack, gate softmax -----------
#define N4X (M_TOT * IN_F / 4)
#define N4W (OUT_F * IN_F / 4)
#define N4A (ERDIM * IN_F / 4)
#define N4TOT (N4X + N4W + N4A)
#define NBMT (OUT_F * ERDIM)

__global__ void prep_kernel(const float* __restrict__ x,
                            const float* __restrict__ W,
                            const float* __restrict__ A,
                            const float* __restrict__ Bm,
                            const float* __restrict__ z,
                            const float* __restrict__ Wg,
                            const float* __restrict__ bg) {
    const int stride = gridDim.x * blockDim.x;
    for (int i = blockIdx.x * blockDim.x + threadIdx.x; i < N4TOT; i += stride) {
        const float4* s; float4* d; int j = i;
        if (j < N4X)               { s = (const float4*)x + j; d = (float4*)g_xt + j; }
        else if ((j -= N4X) < N4W) { s = (const float4*)W + j; d = (float4*)g_Wt + j; }
        else { j -= N4W;             s = (const float4*)A + j; d = (float4*)g_At + j; }
        float4 v = *s;
        v.x = __uint_as_float(f2tf32(v.x));
        v.y = __uint_as_float(f2tf32(v.y));
        v.z = __uint_as_float(f2tf32(v.z));
        v.w = __uint_as_float(f2tf32(v.w));
        *d = v;
    }
    for (int i = blockIdx.x * blockDim.x + threadIdx.x; i < NBMT; i += stride) {
        int o = i >> 7, j = i & 127;
        int e = j >> 4, r = j & 15;
        g_BmT[i] = __uint_as_float(f2tf32(Bm[((size_t)e * OUT_F + o) * NR + r]));
    }
    if (blockIdx.x == 0) {
        __shared__ float sl[NBATCH][NE];
        int tid = threadIdx.x;
        if (tid < 64) {
            int b = tid >> 3, e = tid & 7;
            float s = bg[e];
#pragma unroll
            for (int g = 0; g < GD; g++) s += z[b * GD + g] * Wg[e * GD + g];
            sl[b][e] = s;
        }
        __syncthreads();
        if (tid < NBATCH) {
            float mx = -1e30f;
            for (int k = 0; k < NE; k++) mx = fmaxf(mx, sl[tid][k]);
            float ex[NE]; float den = 0.f;
            for (int k = 0; k < NE; k++) { ex[k] = expf(sl[tid][k] - mx); den += ex[k]; }
            float inv = 1.f / den;
            for (int k = 0; k < NE; k++) g_gate[tid * NE + k] = ex[k] * inv;
        }
    }
}

// ---- kernel: g_h = round_tf32(SCALING * gate ⊙ (xt @ At^T)) ---------------
// 128x128 tile, warp 64x32, 3-stage pipeline (R11 layout, unchanged).
static __device__ __forceinline__ void compute_h(const uint32_t (*As)[SPAD],
                                                 const uint32_t (*Bs)[SPAD],
                                                 int wm, int wn, int g, int t,
                                                 float acc[4][4][4]) {
#pragma unroll
    for (int kk = 0; kk < 4; kk++) {
        const int k8 = kk * 8;
        uint32_t af[4][4], bf[4][2];
#pragma unroll
        for (int mi = 0; mi < 4; mi++) {
            const int m = wm * 64 + mi * 16 + g;
            af[mi][0] = As[m][k8 + t];
            af[mi][1] = As[m + 8][k8 + t];
            af[mi][2] = As[m][k8 + t + 4];
            af[mi][3] = As[m + 8][k8 + t + 4];
        }
#pragma unroll
        for (int ni = 0; ni < 4; ni++) {
            const int n = wn * 32 + ni * 8 + g;
            bf[ni][0] = Bs[n][k8 + t];
            bf[ni][1] = Bs[n][k8 + t + 4];
        }
#pragma unroll
        for (int mi = 0; mi < 4; mi++)
#pragma unroll
            for (int ni = 0; ni < 4; ni++)
                mma_tf32(acc[mi][ni], af[mi], bf[ni]);
    }
}

__global__ __launch_bounds__(256, 2)
void h_mma_kernel() {
    extern __shared__ uint32_t smem[];
    const uint32_t sb = smem_u32(smem);
    const int tid = threadIdx.x, warp = tid >> 5, lane = tid & 31;
    const int wm = warp >> 2, wn = warp & 3;
    const int g = lane >> 2, t = lane & 3;
    const int m0 = blockIdx.x * H_BM;

    float acc[4][4][4];
#pragma unroll
    for (int i = 0; i < 4; i++)
#pragma unroll
        for (int j = 0; j < 4; j++)
#pragma unroll
            for (int r = 0; r < 4; r++) acc[i][j][r] = 0.f;

    const int T = IN_F / BK;   // 24
#pragma unroll
    for (int s = 0; s < 2; s++) {
        load_tile<128>(sb + s * (H_TILE_WORDS * 4), g_xt, IN_F, m0, s * BK, tid);
        load_tile<128>(sb + (NSTAGE + s) * (H_TILE_WORDS * 4), g_At, IN_F, 0, s * BK, tid);
        CP_COMMIT();
    }
    for (int tt = 0; tt < T; tt++) {
        CP_WAIT1();
        __syncthreads();
        const int ts = tt + 2;
        if (ts < T) {
            const int s = ts % NSTAGE;
            load_tile<128>(sb + s * (H_TILE_WORDS * 4), g_xt, IN_F, m0, ts * BK, tid);
            load_tile<128>(sb + (NSTAGE + s) * (H_TILE_WORDS * 4), g_At, IN_F, 0, ts * BK, tid);
        }
        CP_COMMIT();
        const int c = tt % NSTAGE;
        compute_h((const uint32_t (*)[SPAD])(smem + c * H_TILE_WORDS),
                  (const uint32_t (*)[SPAD])(smem + (NSTAGE + c) * H_TILE_WORDS),
                  wm, wn, g, t, acc);
    }

    const int bt = m0 >> 11;            // 128-row tile lies in one batch
#pragma unroll
    for (int mi = 0; mi < 4; mi++) {
        const int row = m0 + wm * 64 + mi * 16 + g;
#pragma unroll
        for (int ni = 0; ni < 4; ni++) {
            const int col = wn * 32 + ni * 8 + 2 * t;   // even; pair same expert
            const float s = SCALING * g_gate[bt * NE + (col >> 4)];
            float2 v0, v1;
            v0.x = __uint_as_float(f2tf32(acc[mi][ni][0] * s));
            v0.y = __uint_as_float(f2tf32(acc[mi][ni][1] * s));
            v1.x = __uint_as_float(f2tf32(acc[mi][ni][2] * s));
            v1.y = __uint_as_float(f2tf32(acc[mi][ni][3] * s));
            *(float2*)(g_h + (size_t)row * ERDIM + col) = v0;
            *(float2*)(g_h + (size_t)(row + 8) * ERDIM + col) = v1;
        }
    }
}

// ---- main kernel: out = xt@Wt^T + bias + g_h@BmT^T, 128x256, warp 64x64 ----
static __device__ __forceinline__ void main_load_stage(uint32_t sb, int ts,
                                                       int m0, int n0, int tid) {
    const int s = ts % NSTAGE;
    const uint32_t base = sb + (uint32_t)s * (STAGE_WORDS * 4);
    if (ts < IN_F / BK) {
        load_tile<128>(base, g_xt, IN_F, m0, ts * BK, tid);
        load_tile<256>(base + TA_WORDS * 4, g_Wt, IN_F, n0, ts * BK, tid);
    } else {
        const int k0 = (ts - IN_F / BK) * BK;
        load_tile<128>(base, g_h, ERDIM, m0, k0, tid);
        load_tile<256>(base + TA_WORDS * 4, g_BmT, ERDIM, n0, k0, tid);
    }
}

__global__ __launch_bounds__(256)
void main_mma_kernel(const float* __restrict__ bias, float* __restrict__ out) {
    extern __shared__ uint32_t smem[];
    const uint32_t sb = smem_u32(smem);
    const int tid = threadIdx.x, warp = tid >> 5, lane = tid & 31;
    const int wm = warp >> 2, wn = warp & 3;       // wm 0..1, wn 0..3
    const int g = lane >> 2, t = lane & 3;
    const int m0 = blockIdx.y * M_BM, n0 = blockIdx.x * M_BN;

    float acc[4][8][4];
#pragma unroll
    for (int i = 0; i < 4; i++)
#pragma unroll
        for (int j = 0; j < 8; j++)
#pragma unroll
            for (int r = 0; r < 4; r++) acc[i][j][r] = 0.f;

    const int T = IN_F / BK + ERDIM / BK;   // 28
#pragma unroll
    for (int s = 0; s < 2; s++) {
        main_load_stage(sb, s, m0, n0, tid);
        CP_COMMIT();
    }
    for (int tt = 0; tt < T; tt++) {
        CP_WAIT1();
        __syncthreads();
        if (tt + 2 < T) main_load_stage(sb, tt + 2, m0, n0, tid);
        CP_COMMIT();
        const int c = tt % NSTAGE;
        const uint32_t (*As)[SPAD] =
            (const uint32_t (*)[SPAD])(smem + c * STAGE_WORDS);
        const uint32_t (*Bs)[SPAD] =
            (const uint32_t (*)[SPAD])(smem + c * STAGE_WORDS + TA_WORDS);
#pragma unroll
        for (int kk = 0; kk < 4; kk++) {
            const int k8 = kk * 8;
            uint32_t af[4][4], bf[8][2];
#pragma unroll
            for (int mi = 0; mi < 4; mi++) {
                const int m = wm * 64 + mi * 16 + g;
                af[mi][0] = As[m][k8 + t];
                af[mi][1] = As[m + 8][k8 + t];
                af[mi][2] = As[m][k8 + t + 4];
                af[mi][3] = As[m + 8][k8 + t + 4];
            }
#pragma unroll
            for (int ni = 0; ni < 8; ni++) {
                const int n = wn * 64 + ni * 8 + g;
                bf[ni][0] = Bs[n][k8 + t];
                bf[ni][1] = Bs[n][k8 + t + 4];
            }
#pragma unroll
            for (int mi = 0; mi < 4; mi++)
#pragma unroll
                for (int ni = 0; ni < 8; ni++)
                    mma_tf32(acc[mi][ni], af[mi], bf[ni]);
        }
    }

#pragma unroll
    for (int mi = 0; mi < 4; mi++) {
        const int row = m0 + wm * 64 + mi * 16 + g;
#pragma unroll
        for (int ni = 0; ni < 8; ni++) {
            const int col = n0 + wn * 64 + ni * 8 + 2 * t;
            const float2 bb = *(const float2*)(bias + col);
            float2 v0 = make_float2(acc[mi][ni][0] + bb.x, acc[mi][ni][1] + bb.y);
            float2 v1 = make_float2(acc[mi][ni][2] + bb.x, acc[mi][ni][3] + bb.y);
            *(float2*)(out + (size_t)row * OUT_F + col) = v0;
            *(float2*)(out + (size_t)(row + 8) * OUT_F + col) = v1;
        }
    }
}

// ---------------------------------------------------------------------------
extern "C" void kernel_launch(void* const* d_in, const int* in_sizes, int n_in,
                              void* d_out, int out_size) {
    const float* x  = (const float*)d_in[0];   // [8,2048,768]
    const float* z  = (const float*)d_in[1];   // [8,64]
    const float* W  = (const float*)d_in[2];   // [2304,768]
    const float* b  = (const float*)d_in[3];   // [2304]
    const float* A  = (const float*)d_in[4];   // [8,16,768]
    const float* Bm = (const float*)d_in[5];   // [8,2304,16]
    const float* Wg = (const float*)d_in[6];   // [8,64]
    const float* bg = (const float*)d_in[7];   // [8]
    float* out = (float*)d_out;                // [8,2048,2304]

    static int attr_done = 0;
    if (!attr_done) {
        cudaFuncSetAttribute(h_mma_kernel,
                             cudaFuncAttributeMaxDynamicSharedMemorySize, H_SMEM_BYTES);
        cudaFuncSetAttribute(main_mma_kernel,
                             cudaFuncAttributeMaxDynamicSharedMemorySize, M_SMEM_BYTES);
        attr_done = 1;
    }

    // fused prologue (tf32 rounding of x/W/A + BmT repack + gate softmax)
    prep_kernel<<<1184, 1024>>>(x, W, A, Bm, z, Wg, bg);

    // LoRA down-projection (gated, scaled, tf32-rounded)
    h_mma_kernel<<<M_TOT / H_BM, 256, H_SMEM_BYTES>>>();

    // fused frozen + LoRA up-projection
    main_mma_kernel<<<dim3(OUT_F / M_BN, M_TOT / M_BM), 256, M_SMEM_BYTES>>>(b, out);
}

// round 13
// speedup vs baseline: 2.7542x; 1.6063x over previous
#include <cuda_runtime.h>
#include <cuda_fp16.h>
#include <cstdint>

// ---------------------------------------------------------------------------
// SpectraLoRA fused, round 13: fp16 mma.sync (m16n8k16, fp32 accumulate).
// Diagnosis: tf32 mma.sync saturates sm_103's legacy HMMA pipe at ~512
// FLOP/cyc/SM (three different smem configs all hit ~467us). fp16 mma.sync
// runs 2x that rate with the SAME 11-bit mantissa as tf32 -> same accuracy.
//   gate[b,e] = softmax(z@Wg^T+bg); BmT repack; g_h = gate-scaled x@A^T;
//   out = x@W^T + bias + g_h@BmT^T  (K=768 + K=128 in one accumulator).
// Smem: halves, row stride 40 (20 words) -> fragment LDS conflict-free.
// ---------------------------------------------------------------------------

#define IN_F   768
#define OUT_F  2304
#define NBATCH 8
#define M_TOT  16384
#define NE     8
#define NR     16
#define ERDIM  128
#define GD     64
#define SCALING 2.0f

#define BM 128
#define BN 128
#define BK 32
#define SPADW 20                        // words per smem row (16 data + 4 pad)
#define TILE_WORDS (BM * SPADW)         // 2560 words = 10240 B per tile
#define NSTAGE 3
#define SMEM_BYTES (2 * NSTAGE * TILE_WORDS * 4)   // 61440 B

__device__ float  g_gate[NBATCH * NE];
__device__ __half g_BmTh[OUT_F * ERDIM];
__device__ __half g_hh[(size_t)M_TOT * ERDIM];
__device__ __half g_xh[(size_t)M_TOT * IN_F];
__device__ __half g_Wh[(size_t)OUT_F * IN_F];
__device__ __half g_Ah[ERDIM * IN_F];

// ---- helpers ---------------------------------------------------------------
static __device__ __forceinline__ void mma_f16(float d[4], const uint32_t a[4],
                                               const uint32_t b[2]) {
    asm volatile(
        "mma.sync.aligned.m16n8k16.row.col.f32.f16.f16.f32 "
        "{%0,%1,%2,%3}, {%4,%5,%6,%7}, {%8,%9}, {%0,%1,%2,%3};"
        : "+f"(d[0]), "+f"(d[1]), "+f"(d[2]), "+f"(d[3])
        : "r"(a[0]), "r"(a[1]), "r"(a[2]), "r"(a[3]), "r"(b[0]), "r"(b[1]));
}
static __device__ __forceinline__ uint32_t smem_u32(const void* p) {
    uint32_t a;
    asm("{ .reg .u64 t; cvta.to.shared.u64 t, %1; cvt.u32.u64 %0, t; }"
        : "=r"(a) : "l"(p));
    return a;
}
static __device__ __forceinline__ void cpasync16(uint32_t dst, const void* src) {
    asm volatile("cp.async.cg.shared.global [%0], [%1], 16;"
                 :: "r"(dst), "l"(src) : "memory");
}
#define CP_COMMIT() asm volatile("cp.async.commit_group;" ::: "memory")
#define CP_WAIT1()  asm volatile("cp.async.wait_group 1;" ::: "memory")

// 256 threads load a ROWSx32 half tile (64 B/row = 4 x 16 B):
// kq = tid&3 (16B chunk), r0 = tid>>2 (0..63), rows r0 + 64*i.
template <int ROWS>
static __device__ __forceinline__ void load_tile(uint32_t sdst,
                                                 const __half* __restrict__ src,
                                                 int ld, int row0, int k0,
                                                 int tid) {
    const int kq = tid & 3, r0 = tid >> 2;
    const __half* gp = src + (size_t)(row0 + r0) * ld + k0 + kq * 8;
    uint32_t d = sdst + ((uint32_t)r0 * SPADW + (uint32_t)kq * 4) * 4;
#pragma unroll
    for (int i = 0; i < ROWS / 64; i++)
        cpasync16(d + i * (64 * SPADW * 4), gp + (size_t)(64 * i) * ld);
}

// warp tile 64x32 over one BK=32 slab (2 x k16 steps); acc[4][4][4]
static __device__ __forceinline__ void compute_tile(const uint32_t* As,
                                                    const uint32_t* Bs,
                                                    int wm, int wn, int g, int t,
                                                    float acc[4][4][4]) {
#pragma unroll
    for (int kk = 0; kk < 2; kk++) {
        const int kb = kk * 8;          // k16 step = 16 halves = 8 words
        uint32_t af[4][4], bf[4][2];
#pragma unroll
        for (int mi = 0; mi < 4; mi++) {
            const int m = wm * 64 + mi * 16 + g;
            af[mi][0] = As[m * SPADW + kb + t];
            af[mi][1] = As[(m + 8) * SPADW + kb + t];
            af[mi][2] = As[m * SPADW + kb + t + 4];
            af[mi][3] = As[(m + 8) * SPADW + kb + t + 4];
        }
#pragma unroll
        for (int ni = 0; ni < 4; ni++) {
            const int n = wn * 32 + ni * 8 + g;
            bf[ni][0] = Bs[n * SPADW + kb + t];
            bf[ni][1] = Bs[n * SPADW + kb + t + 4];
        }
#pragma unroll
        for (int mi = 0; mi < 4; mi++)
#pragma unroll
            for (int ni = 0; ni < 4; ni++)
                mma_f16(acc[mi][ni], af[mi], bf[ni]);
    }
}

// ---- fused prologue: cvt x/W/A to fp16, BmT repack, gate softmax -----------
#define N4X (M_TOT * IN_F / 4)
#define N4W (OUT_F * IN_F / 4)
#define N4A (ERDIM * IN_F / 4)
#define N4TOT (N4X + N4W + N4A)
#define NBMT (OUT_F * ERDIM)

__global__ void prep_kernel(const float* __restrict__ x,
                            const float* __restrict__ W,
                            const float* __restrict__ A,
                            const float* __restrict__ Bm,
                            const float* __restrict__ z,
                            const float* __restrict__ Wg,
                            const float* __restrict__ bg) {
    const int stride = gridDim.x * blockDim.x;
    for (int i = blockIdx.x * blockDim.x + threadIdx.x; i < N4TOT; i += stride) {
        const float4* s; __half* d; int j = i;
        if (j < N4X)               { s = (const float4*)x + j; d = g_xh + 4 * (size_t)j; }
        else if ((j -= N4X) < N4W) { s = (const float4*)W + j; d = g_Wh + 4 * (size_t)j; }
        else { j -= N4W;             s = (const float4*)A + j; d = g_Ah + 4 * (size_t)j; }
        float4 v = *s;
        __half2 h0 = __floats2half2_rn(v.x, v.y);
        __half2 h1 = __floats2half2_rn(v.z, v.w);
        uint2 u;
        u.x = *(uint32_t*)&h0; u.y = *(uint32_t*)&h1;
        *(uint2*)d = u;
    }
    for (int i = blockIdx.x * blockDim.x + threadIdx.x; i < NBMT; i += stride) {
        int o = i >> 7, j = i & 127;
        int e = j >> 4, r = j & 15;
        g_BmTh[i] = __float2half_rn(Bm[((size_t)e * OUT_F + o) * NR + r]);
    }
    if (blockIdx.x == 0) {
        __shared__ float sl[NBATCH][NE];
        int tid = threadIdx.x;
        if (tid < 64) {
            int b = tid >> 3, e = tid & 7;
            float s = bg[e];
#pragma unroll
            for (int g = 0; g < GD; g++) s += z[b * GD + g] * Wg[e * GD + g];
            sl[b][e] = s;
        }
        __syncthreads();
        if (tid < NBATCH) {
            float mx = -1e30f;
            for (int k = 0; k < NE; k++) mx = fmaxf(mx, sl[tid][k]);
            float ex[NE]; float den = 0.f;
            for (int k = 0; k < NE; k++) { ex[k] = expf(sl[tid][k] - mx); den += ex[k]; }
            float inv = 1.f / den;
            for (int k = 0; k < NE; k++) g_gate[tid * NE + k] = ex[k] * inv;
        }
    }
}

// ---- kernel: g_hh = half(SCALING * gate ⊙ (xh @ Ah^T)) ---------------------
__global__ __launch_bounds__(256, 2)
void h_mma_kernel() {
    extern __shared__ uint32_t smem[];
    const uint32_t sb = smem_u32(smem);
    const int tid = threadIdx.x, warp = tid >> 5, lane = tid & 31;
    const int wm = warp >> 2, wn = warp & 3;
    const int g = lane >> 2, t = lane & 3;
    const int m0 = blockIdx.x * BM;

    float acc[4][4][4];
#pragma unroll
    for (int i = 0; i < 4; i++)
#pragma unroll
        for (int j = 0; j < 4; j++)
#pragma unroll
            for (int r = 0; r < 4; r++) acc[i][j][r] = 0.f;

    const int T = IN_F / BK;   // 24
#pragma unroll
    for (int s = 0; s < 2; s++) {
        load_tile<128>(sb + s * (TILE_WORDS * 4), g_xh, IN_F, m0, s * BK, tid);
        load_tile<128>(sb + (NSTAGE + s) * (TILE_WORDS * 4), g_Ah, IN_F, 0, s * BK, tid);
        CP_COMMIT();
    }
    for (int tt = 0; tt < T; tt++) {
        CP_WAIT1();
        __syncthreads();
        const int ts = tt + 2;
        if (ts < T) {
            const int s = ts % NSTAGE;
            load_tile<128>(sb + s * (TILE_WORDS * 4), g_xh, IN_F, m0, ts * BK, tid);
            load_tile<128>(sb + (NSTAGE + s) * (TILE_WORDS * 4), g_Ah, IN_F, 0, ts * BK, tid);
        }
        CP_COMMIT();
        const int c = tt % NSTAGE;
        compute_tile(smem + c * TILE_WORDS, smem + (NSTAGE + c) * TILE_WORDS,
                     wm, wn, g, t, acc);
    }

    const int bt = m0 >> 11;            // 128-row tile lies in one batch
#pragma unroll
    for (int mi = 0; mi < 4; mi++) {
        const int row = m0 + wm * 64 + mi * 16 + g;
#pragma unroll
        for (int ni = 0; ni < 4; ni++) {
            const int col = wn * 32 + ni * 8 + 2 * t;   // pair within one expert
            const float s = SCALING * g_gate[bt * NE + (col >> 4)];
            __half2 h0 = __floats2half2_rn(acc[mi][ni][0] * s, acc[mi][ni][1] * s);
            __half2 h1 = __floats2half2_rn(acc[mi][ni][2] * s, acc[mi][ni][3] * s);
            *(__half2*)(g_hh + (size_t)row * ERDIM + col) = h0;
            *(__half2*)(g_hh + (size_t)(row + 8) * ERDIM + col) = h1;
        }
    }
}

// ---- kernel: out = xh@Wh^T + bias + g_hh@BmTh^T ----------------------------
static __device__ __forceinline__ void main_load_stage(uint32_t sb, int ts,
                                                       int m0, int n0, int tid) {
    const int s = ts % NSTAGE;
    if (ts < IN_F / BK) {
        load_tile<128>(sb + s * (TILE_WORDS * 4), g_xh, IN_F, m0, ts * BK, tid);
        load_tile<128>(sb + (NSTAGE + s) * (TILE_WORDS * 4), g_Wh, IN_F, n0, ts * BK, tid);
    } else {
        const int k0 = (ts - IN_F / BK) * BK;
        load_tile<128>(sb + s * (TILE_WORDS * 4), g_hh, ERDIM, m0, k0, tid);
        load_tile<128>(sb + (NSTAGE + s) * (TILE_WORDS * 4), g_BmTh, ERDIM, n0, k0, tid);
    }
}

__global__ __launch_bounds__(256, 2)
void main_mma_kernel(const float* __restrict__ bias, float* __restrict__ out) {
    extern __shared__ uint32_t smem[];
    const uint32_t sb = smem_u32(smem);
    const int tid = threadIdx.x, warp = tid >> 5, lane = tid & 31;
    const int wm = warp >> 2, wn = warp & 3;
    const int g = lane >> 2, t = lane & 3;
    const int m0 = blockIdx.y * BM, n0 = blockIdx.x * BN;

    float acc[4][4][4];
#pragma unroll
    for (int i = 0; i < 4; i++)
#pragma unroll
        for (int j = 0; j < 4; j++)
#pragma unroll
            for (int r = 0; r < 4; r++) acc[i][j][r] = 0.f;

    const int T = IN_F / BK + ERDIM / BK;   // 28
#pragma unroll
    for (int s = 0; s < 2; s++) {
        main_load_stage(sb, s, m0, n0, tid);
        CP_COMMIT();
    }
    for (int tt = 0; tt < T; tt++) {
        CP_WAIT1();
        __syncthreads();
        if (tt + 2 < T) main_load_stage(sb, tt + 2, m0, n0, tid);
        CP_COMMIT();
        const int c = tt % NSTAGE;
        compute_tile(smem + c * TILE_WORDS, smem + (NSTAGE + c) * TILE_WORDS,
                     wm, wn, g, t, acc);
    }

#pragma unroll
    for (int mi = 0; mi < 4; mi++) {
        const int row = m0 + wm * 64 + mi * 16 + g;
#pragma unroll
        for (int ni = 0; ni < 4; ni++) {
            const int col = n0 + wn * 32 + ni * 8 + 2 * t;
            const float2 bb = *(const float2*)(bias + col);
            float2 v0 = make_float2(acc[mi][ni][0] + bb.x, acc[mi][ni][1] + bb.y);
            float2 v1 = make_float2(acc[mi][ni][2] + bb.x, acc[mi][ni][3] + bb.y);
            *(float2*)(out + (size_t)row * OUT_F + col) = v0;
            *(float2*)(out + (size_t)(row + 8) * OUT_F + col) = v1;
        }
    }
}

// ---------------------------------------------------------------------------
extern "C" void kernel_launch(void* const* d_in, const int* in_sizes, int n_in,
                              void* d_out, int out_size) {
    const float* x  = (const float*)d_in[0];   // [8,2048,768]
    const float* z  = (const float*)d_in[1];   // [8,64]
    const float* W  = (const float*)d_in[2];   // [2304,768]
    const float* b  = (const float*)d_in[3];   // [2304]
    const float* A  = (const float*)d_in[4];   // [8,16,768]
    const float* Bm = (const float*)d_in[5];   // [8,2304,16]
    const float* Wg = (const float*)d_in[6];   // [8,64]
    const float* bg = (const float*)d_in[7];   // [8]
    float* out = (float*)d_out;                // [8,2048,2304]

    static int attr_done = 0;
    if (!attr_done) {
        cudaFuncSetAttribute(h_mma_kernel,
                             cudaFuncAttributeMaxDynamicSharedMemorySize, SMEM_BYTES);
        cudaFuncSetAttribute(main_mma_kernel,
                             cudaFuncAttributeMaxDynamicSharedMemorySize, SMEM_BYTES);
        attr_done = 1;
    }

    // fused prologue (fp16 conversion of x/W/A + BmT repack + gate softmax)
    prep_kernel<<<1184, 1024>>>(x, W, A, Bm, z, Wg, bg);

    // LoRA down-projection (gated, scaled, fp16)
    h_mma_kernel<<<M_TOT / BM, 256, SMEM_BYTES>>>();

    // fused frozen + LoRA up-projection
    main_mma_kernel<<<dim3(OUT_F / BN, M_TOT / BM), 256, SMEM_BYTES>>>(b, out);
}